// round 7
// baseline (speedup 1.0000x reference)
#include <cuda_runtime.h>
#include <cuda_bf16.h>
#include <cstdint>

// ---------------------------------------------------------------------------
// TTT layer, B=8, S=2048, D_IN=D_H=1024, fp32.
// Inputs (metadata order): in_seq[8,2048,1024], theta_K[1024,1024],
//   theta_V[1024,1024], theta_Q[1024,1024], W0[1024,1024], b0[1024]
// Output: [8,2048,1024] fp32.
//
// Math (per-dimension decoupling). For each (b, e):
//   d1 = W[e]·k_t ; d2 = W[e]·q_t
//   g  = (2/1024)(d1 + b_e - v_t[e])
//   out_t[e] = d2 + b_e - LR*g*(k_t·q_t + 1)   (== post-update W·q + b)
//   W[e] -= LR*g*k_t ; b_e -= LR*g
// k_t·q_t precomputed per (b,t) by kq_kernel, shared by all e.
// proj: double-buffered SMEM (1 barrier/k-step, LDG hidden under compute).
// scan: warp owns FOUR e-rows; 64-bit-shfl packed-pair butterfly all-reduce.
// ---------------------------------------------------------------------------

#define B_DIM   8
#define S_DIM   2048
#define D_DIM   1024
#define LR_F    0.01f
#define C1_F    (2.0f / 1024.0f)

// Scratch (allocation-free rule: __device__ globals). 16B-aligned.
__device__ __align__(16) float g_K[B_DIM * S_DIM * D_DIM];
__device__ __align__(16) float g_V[B_DIM * S_DIM * D_DIM];
__device__ __align__(16) float g_Q[B_DIM * S_DIM * D_DIM];
__device__ __align__(16) float g_kq[B_DIM * S_DIM];

// ---------------- packed f32x2 helpers (PTX-only on sm_103a) ----------------
struct __align__(16) U2 { unsigned long long x, y; };

__device__ __forceinline__ unsigned long long f2fma(unsigned long long a,
                                                    unsigned long long b,
                                                    unsigned long long c) {
    unsigned long long d;
    asm("fma.rn.f32x2 %0, %1, %2, %3;" : "=l"(d) : "l"(a), "l"(b), "l"(c));
    return d;
}
__device__ __forceinline__ unsigned long long f2add(unsigned long long a,
                                                    unsigned long long b) {
    unsigned long long d;
    asm("add.rn.f32x2 %0, %1, %2;" : "=l"(d) : "l"(a), "l"(b));
    return d;
}
__device__ __forceinline__ unsigned long long f2pack(float lo, float hi) {
    unsigned long long d;
    asm("mov.b64 %0, {%1, %2};" : "=l"(d) : "f"(lo), "f"(hi));
    return d;
}
__device__ __forceinline__ void f2unpack(unsigned long long v, float& lo, float& hi) {
    asm("mov.b64 {%0, %1}, %2;" : "=f"(lo), "=f"(hi) : "l"(v));
}
__device__ __forceinline__ float f2hsum(unsigned long long v) {
    float lo, hi; f2unpack(v, lo, hi);
    return lo + hi;
}
// Butterfly all-reduce of a packed f32x2 pair. 64-bit shfl (2 SHFL) + one
// packed add per stage — no unpack/pack MOVs in the loop.
__device__ __forceinline__ unsigned long long warp_sum_pair(unsigned long long v) {
#pragma unroll
    for (int off = 16; off; off >>= 1) {
        unsigned long long s = __shfl_xor_sync(0xffffffffu, v, off);
        v = f2add(v, s);
    }
    return v;
}

// ---------------------------------------------------------------------------
// Projection GEMM: C[m,e] = sum_d A[m,d] * Th[e,d]   (NT, both K-contiguous)
// M=16384, N=1024, K=1024. 128x128 tile, BK=8, 256 threads, 8x8 microtile,
// f32x2 packed accumulation, DOUBLE-BUFFERED smem: per k-step
//   LDG(next) -> compute(cur) -> STS(next buffer) -> one __syncthreads.
// Overwrite-safety: a buffer is re-written only after the sync that followed
// the compute which last read it. blockIdx.z selects theta -> {g_K,g_V,g_Q}.
// ---------------------------------------------------------------------------
__global__ __launch_bounds__(256, 2) void proj_kernel(
    const float* __restrict__ A,
    const float* __restrict__ thK,
    const float* __restrict__ thV,
    const float* __restrict__ thQ)
{
    constexpr int K = D_DIM, N = D_DIM;
    const float* __restrict__ Bm;
    float* __restrict__ C;
    if (blockIdx.z == 0)      { Bm = thK; C = g_K; }
    else if (blockIdx.z == 1) { Bm = thV; C = g_V; }
    else                      { Bm = thQ; C = g_Q; }

    __shared__ float As[2][8][128];
    __shared__ float Bs[2][8][128];

    const int tid  = threadIdx.x;
    const int m0   = blockIdx.x * 128;
    const int n0   = blockIdx.y * 128;
    const int lrow = tid >> 1;            // 0..127
    const int lcol = (tid & 1) << 2;      // 0 or 4
    const float* Ap = A  + (size_t)(m0 + lrow) * K + lcol;
    const float* Bp = Bm + (size_t)(n0 + lrow) * K + lcol;
    const int tx = tid & 15;
    const int ty = tid >> 4;

    unsigned long long acc[8][4];
#pragma unroll
    for (int i = 0; i < 8; i++)
#pragma unroll
        for (int j = 0; j < 4; j++) acc[i][j] = 0ULL;

    // prologue: stage k0 = 0 into buffer 0
    {
        float4 av = *(const float4*)(Ap);
        float4 bv = *(const float4*)(Bp);
        As[0][lcol + 0][lrow] = av.x; As[0][lcol + 1][lrow] = av.y;
        As[0][lcol + 2][lrow] = av.z; As[0][lcol + 3][lrow] = av.w;
        Bs[0][lcol + 0][lrow] = bv.x; Bs[0][lcol + 1][lrow] = bv.y;
        Bs[0][lcol + 2][lrow] = bv.z; Bs[0][lcol + 3][lrow] = bv.w;
    }
    __syncthreads();

    int buf = 0;
    for (int k0 = 0; k0 < K; k0 += 8) {
        float4 av, bv;
        const bool more = (k0 + 8) < K;
        if (more) {                       // LDG for next step, issued first
            av = *(const float4*)(Ap + k0 + 8);
            bv = *(const float4*)(Bp + k0 + 8);
        }
#pragma unroll
        for (int kk = 0; kk < 8; kk++) { // compute current buffer
            float4 a0 = *(const float4*)&As[buf][kk][ty * 8];
            float4 a1 = *(const float4*)&As[buf][kk][ty * 8 + 4];
            U2 b0 = *(const U2*)&Bs[buf][kk][tx * 8];
            U2 b1 = *(const U2*)&Bs[buf][kk][tx * 8 + 4];
            float a[8] = {a0.x, a0.y, a0.z, a0.w, a1.x, a1.y, a1.z, a1.w};
#pragma unroll
            for (int i = 0; i < 8; i++) {
                unsigned long long ra = f2pack(a[i], a[i]);
                acc[i][0] = f2fma(ra, b0.x, acc[i][0]);
                acc[i][1] = f2fma(ra, b0.y, acc[i][1]);
                acc[i][2] = f2fma(ra, b1.x, acc[i][2]);
                acc[i][3] = f2fma(ra, b1.y, acc[i][3]);
            }
        }
        if (more) {                       // stage next into the other buffer
            const int nb = buf ^ 1;
            As[nb][lcol + 0][lrow] = av.x; As[nb][lcol + 1][lrow] = av.y;
            As[nb][lcol + 2][lrow] = av.z; As[nb][lcol + 3][lrow] = av.w;
            Bs[nb][lcol + 0][lrow] = bv.x; Bs[nb][lcol + 1][lrow] = bv.y;
            Bs[nb][lcol + 2][lrow] = bv.z; Bs[nb][lcol + 3][lrow] = bv.w;
            __syncthreads();
            buf = nb;
        }
    }

#pragma unroll
    for (int i = 0; i < 8; i++) {
        float* cp = C + (size_t)(m0 + ty * 8 + i) * N + n0 + tx * 8;
        U2 v0; v0.x = acc[i][0]; v0.y = acc[i][1];
        U2 v1; v1.x = acc[i][2]; v1.y = acc[i][3];
        *(U2*)cp       = v0;
        *(U2*)(cp + 4) = v1;
    }
}

// ---------------------------------------------------------------------------
// kq_kernel: g_kq[b*S+t] = K[b,t,:] . Q[b,t,:]   (one warp per row)
// ---------------------------------------------------------------------------
__global__ __launch_bounds__(256) void kq_kernel()
{
    const int row  = (blockIdx.x * blockDim.x + threadIdx.x) >> 5; // 0..16383
    const int lane = threadIdx.x & 31;
    const U2* kp = (const U2*)(g_K + (size_t)row * D_DIM);
    const U2* qp = (const U2*)(g_Q + (size_t)row * D_DIM);
    unsigned long long acc = 0ULL;
#pragma unroll
    for (int j = 0; j < 8; j++) {
        U2 k = kp[lane + 32 * j];
        U2 q = qp[lane + 32 * j];
        acc = f2fma(k.x, q.x, acc);
        acc = f2fma(k.y, q.y, acc);
    }
    unsigned long long s = warp_sum_pair(acc);
    if (lane == 0) g_kq[row] = f2hsum(s);
}

// ---------------------------------------------------------------------------
// scan_kernel: warp owns FOUR consecutive e-rows (e0..e0+3) of batch b.
// W rows in registers: 4 x 16 packed u64 / lane = 128 regs. k/q loaded once
// per step, amortized over 4 rows -> 2KB L1 per row (vs 8KB at R=1).
// Reductions: hsum per accumulator, pack (d1[r],d2[r]), 64-bit-shfl butterfly.
// v / kq scalar loads issued before the dot loop (latency hidden under FMAs).
// grid = (32 e-blocks, 8 batches), 256 threads = 8 warps, 1 CTA/SM.
// ---------------------------------------------------------------------------
__global__ __launch_bounds__(256, 1) void scan_kernel(
    const float* __restrict__ W0,
    const float* __restrict__ b0,
    float* __restrict__ out)
{
    const int lane = threadIdx.x & 31;
    const int w    = threadIdx.x >> 5;
    const int b    = blockIdx.y;
    const int e0   = blockIdx.x * 32 + 4 * w;   // multiple of 4

    // init state: W rows e0..e0+3 and biases
    unsigned long long Wr[4][16];
    float bb[4];
#pragma unroll
    for (int r = 0; r < 4; r++) {
        const U2* p = (const U2*)(W0 + (size_t)(e0 + r) * D_DIM);
#pragma unroll
        for (int j = 0; j < 8; j++) {
            U2 t = p[lane + 32 * j];
            Wr[r][2 * j] = t.x; Wr[r][2 * j + 1] = t.y;
        }
        bb[r] = b0[e0 + r];
    }

    const size_t base = (size_t)b * S_DIM * D_DIM;
    const float4* Vp  = (const float4*)(g_V + base + e0);   // e0 % 4 == 0
    const float*  kqp = g_kq + (size_t)b * S_DIM;
    float4* outp      = (float4*)(out + base + e0);

    for (int t = 0; t < S_DIM; t++) {
        // issue scalar epilogue loads first — hidden under the dot FMAs
        float4 v  = Vp[(size_t)t * (D_DIM / 4)];
        float kq1 = kqp[t] + 1.0f;

        const U2* kp = (const U2*)(g_K + base + (size_t)t * D_DIM);
        const U2* qp = (const U2*)(g_Q + base + (size_t)t * D_DIM);
        unsigned long long ak[4] = {0ULL, 0ULL, 0ULL, 0ULL};
        unsigned long long aq[4] = {0ULL, 0ULL, 0ULL, 0ULL};
        U2 ksave[8];
#pragma unroll
        for (int j = 0; j < 8; j++) {
            U2 kj = kp[lane + 32 * j];
            U2 qj = qp[lane + 32 * j];
            ksave[j] = kj;
#pragma unroll
            for (int r = 0; r < 4; r++) {
                ak[r] = f2fma(Wr[r][2 * j],     kj.x, ak[r]);
                ak[r] = f2fma(Wr[r][2 * j + 1], kj.y, ak[r]);
                aq[r] = f2fma(Wr[r][2 * j],     qj.x, aq[r]);
                aq[r] = f2fma(Wr[r][2 * j + 1], qj.y, aq[r]);
            }
        }
        // pack (d1[r], d2[r]) per row, butterfly pairs across the warp
        float d1[4], d2[4];
#pragma unroll
        for (int r = 0; r < 4; r++) {
            unsigned long long pr = f2pack(f2hsum(ak[r]), f2hsum(aq[r]));
            pr = warp_sum_pair(pr);
            f2unpack(pr, d1[r], d2[r]);
        }
        float og[4];
        og[0] = (LR_F * C1_F) * (d1[0] + bb[0] - v.x);
        og[1] = (LR_F * C1_F) * (d1[1] + bb[1] - v.y);
        og[2] = (LR_F * C1_F) * (d1[2] + bb[2] - v.z);
        og[3] = (LR_F * C1_F) * (d1[3] + bb[3] - v.w);
        if (lane == 0) {
            float4 o;
            o.x = d2[0] + bb[0] - og[0] * kq1;
            o.y = d2[1] + bb[1] - og[1] * kq1;
            o.z = d2[2] + bb[2] - og[2] * kq1;
            o.w = d2[3] + bb[3] - og[3] * kq1;
            outp[(size_t)t * (D_DIM / 4)] = o;
        }
        unsigned long long nog[4];
#pragma unroll
        for (int r = 0; r < 4; r++) nog[r] = f2pack(-og[r], -og[r]);
#pragma unroll
        for (int j = 0; j < 8; j++) {
#pragma unroll
            for (int r = 0; r < 4; r++) {
                Wr[r][2 * j]     = f2fma(nog[r], ksave[j].x, Wr[r][2 * j]);
                Wr[r][2 * j + 1] = f2fma(nog[r], ksave[j].y, Wr[r][2 * j + 1]);
            }
        }
#pragma unroll
        for (int r = 0; r < 4; r++) bb[r] -= og[r];
    }
}

// ---------------------------------------------------------------------------
extern "C" void kernel_launch(void* const* d_in, const int* in_sizes, int n_in,
                              void* d_out, int out_size)
{
    (void)in_sizes; (void)n_in; (void)out_size;
    const float* in_seq = (const float*)d_in[0];
    const float* thK    = (const float*)d_in[1];
    const float* thV    = (const float*)d_in[2];
    const float* thQ    = (const float*)d_in[3];
    const float* W0     = (const float*)d_in[4];
    const float* b0     = (const float*)d_in[5];
    float* out          = (float*)d_out;

    // 1) K/V/Q projections: [16384,1024] x [1024,1024]^T, z selects theta
    dim3 pgrid(16384 / 128, D_DIM / 128, 3);
    proj_kernel<<<pgrid, 256>>>(in_seq, thK, thV, thQ);

    // 2) per-token k.q
    kq_kernel<<<(B_DIM * S_DIM) / 8, 256>>>();

    // 3) sequential scan, warp per (b, 4 e-rows)
    dim3 sgrid(D_DIM / 32, B_DIM);
    scan_kernel<<<sgrid, 256>>>(W0, b0, out);
}

// round 11
// speedup vs baseline: 1.1050x; 1.1050x over previous
#include <cuda_runtime.h>
#include <cuda_bf16.h>
#include <cstdint>

// ---------------------------------------------------------------------------
// TTT layer, B=8, S=2048, D_IN=D_H=1024, fp32.
// R11 == audited R9 design (never yet run on HW):
//   proj -> 128x256 tile, 8x16 microtile with CHUNKED B fragment
//     (n = tx*4 + g*64): conflict-free LDS.128, 0.75 B/FMA. R7 evidence
//     showed L1=92%/fma=56% from 4-way B-read bank conflicts.
//   scan -> CTA-cooperative double-buffered SMEM staging of k/q
//     (removes the exposed per-j LDG latency chain behind R7's ~4.8ms scan).
// ---------------------------------------------------------------------------

#define B_DIM   8
#define S_DIM   2048
#define D_DIM   1024
#define LR_F    0.01f
#define C1_F    (2.0f / 1024.0f)

__device__ __align__(16) float g_K[B_DIM * S_DIM * D_DIM];
__device__ __align__(16) float g_V[B_DIM * S_DIM * D_DIM];
__device__ __align__(16) float g_Q[B_DIM * S_DIM * D_DIM];
__device__ __align__(16) float g_kq[B_DIM * S_DIM];

// ---------------- packed f32x2 helpers (PTX-only on sm_103a) ----------------
struct __align__(16) U2 { unsigned long long x, y; };

__device__ __forceinline__ unsigned long long f2fma(unsigned long long a,
                                                    unsigned long long b,
                                                    unsigned long long c) {
    unsigned long long d;
    asm("fma.rn.f32x2 %0, %1, %2, %3;" : "=l"(d) : "l"(a), "l"(b), "l"(c));
    return d;
}
__device__ __forceinline__ unsigned long long f2add(unsigned long long a,
                                                    unsigned long long b) {
    unsigned long long d;
    asm("add.rn.f32x2 %0, %1, %2;" : "=l"(d) : "l"(a), "l"(b));
    return d;
}
__device__ __forceinline__ unsigned long long f2pack(float lo, float hi) {
    unsigned long long d;
    asm("mov.b64 %0, {%1, %2};" : "=l"(d) : "f"(lo), "f"(hi));
    return d;
}
__device__ __forceinline__ void f2unpack(unsigned long long v, float& lo, float& hi) {
    asm("mov.b64 {%0, %1}, %2;" : "=f"(lo), "=f"(hi) : "l"(v));
}
__device__ __forceinline__ float f2hsum(unsigned long long v) {
    float lo, hi; f2unpack(v, lo, hi);
    return lo + hi;
}
// Butterfly all-reduce of a packed f32x2 pair (64-bit shfl + packed add).
__device__ __forceinline__ unsigned long long warp_sum_pair(unsigned long long v) {
#pragma unroll
    for (int off = 16; off; off >>= 1) {
        unsigned long long s = __shfl_xor_sync(0xffffffffu, v, off);
        v = f2add(v, s);
    }
    return v;
}

// ---------------------------------------------------------------------------
// Projection GEMM: C[m,e] = sum_d A[m,d] * Th[e,d]   (NT, both K-contiguous)
// 128x256 tile, BK=8, 256 threads, 8 m-rows x 16 n-cols per thread.
// B fragment is CHUNKED: n = tx*4 + g*64 (g=0..3) -> LDS.128 banks
// tx*4 % 32 distinct within each 8-lane phase => conflict-free.
// Double-buffered SMEM, one __syncthreads per k-step.
// ---------------------------------------------------------------------------
__global__ __launch_bounds__(256, 1) void proj_kernel(
    const float* __restrict__ A,
    const float* __restrict__ thK,
    const float* __restrict__ thV,
    const float* __restrict__ thQ)
{
    constexpr int K = D_DIM, N = D_DIM;
    const float* __restrict__ Bm;
    float* __restrict__ C;
    if (blockIdx.z == 0)      { Bm = thK; C = g_K; }
    else if (blockIdx.z == 1) { Bm = thV; C = g_V; }
    else                      { Bm = thQ; C = g_Q; }

    __shared__ __align__(16) float As[2][8][128];
    __shared__ __align__(16) float Bs[2][8][256];

    const int tid  = threadIdx.x;
    const int m0   = blockIdx.x * 128;
    const int n0   = blockIdx.y * 256;
    const int lrow = tid >> 1;            // 0..127 (A stage row)
    const int lcol = (tid & 1) << 2;      // 0 or 4 (A stage k-offset)
    const float* Ap = A  + (size_t)(m0 + lrow) * K + lcol;
    const float* Bp = Bm + (size_t)(n0 + tid) * K;   // one theta row per thread
    const int tx = tid & 15;              // n-group
    const int ty = tid >> 4;              // m-block 0..15 (8 rows each)

    unsigned long long acc[8][8];         // [m-row][chunk g*2 + half]
#pragma unroll
    for (int i = 0; i < 8; i++)
#pragma unroll
        for (int j = 0; j < 8; j++) acc[i][j] = 0ULL;

    // prologue: stage k0 = 0 into buffer 0
    {
        float4 av  = *(const float4*)(Ap);
        float4 bv0 = *(const float4*)(Bp);
        float4 bv1 = *(const float4*)(Bp + 4);
        As[0][lcol + 0][lrow] = av.x; As[0][lcol + 1][lrow] = av.y;
        As[0][lcol + 2][lrow] = av.z; As[0][lcol + 3][lrow] = av.w;
        Bs[0][0][tid] = bv0.x; Bs[0][1][tid] = bv0.y;
        Bs[0][2][tid] = bv0.z; Bs[0][3][tid] = bv0.w;
        Bs[0][4][tid] = bv1.x; Bs[0][5][tid] = bv1.y;
        Bs[0][6][tid] = bv1.z; Bs[0][7][tid] = bv1.w;
    }
    __syncthreads();

    int buf = 0;
    for (int k0 = 0; k0 < K; k0 += 8) {
        float4 av, bv0, bv1;
        const bool more = (k0 + 8) < K;
        if (more) {                       // next step's LDG, issued first
            av  = *(const float4*)(Ap + k0 + 8);
            bv0 = *(const float4*)(Bp + k0 + 8);
            bv1 = *(const float4*)(Bp + k0 + 12);
        }
#pragma unroll
        for (int kk = 0; kk < 8; kk++) { // compute current buffer
            float4 a0 = *(const float4*)&As[buf][kk][ty * 8];
            float4 a1 = *(const float4*)&As[buf][kk][ty * 8 + 4];
            // chunked B: 4 x LDS.128, conflict-free
            U2 bg[4];
#pragma unroll
            for (int g = 0; g < 4; g++)
                bg[g] = *(const U2*)&Bs[buf][kk][tx * 4 + g * 64];
            float a[8] = {a0.x, a0.y, a0.z, a0.w, a1.x, a1.y, a1.z, a1.w};
#pragma unroll
            for (int i = 0; i < 8; i++) {
                unsigned long long ra = f2pack(a[i], a[i]);
#pragma unroll
                for (int g = 0; g < 4; g++) {
                    acc[i][2 * g]     = f2fma(ra, bg[g].x, acc[i][2 * g]);
                    acc[i][2 * g + 1] = f2fma(ra, bg[g].y, acc[i][2 * g + 1]);
                }
            }
        }
        if (more) {                       // stage next into the other buffer
            const int nb = buf ^ 1;
            As[nb][lcol + 0][lrow] = av.x; As[nb][lcol + 1][lrow] = av.y;
            As[nb][lcol + 2][lrow] = av.z; As[nb][lcol + 3][lrow] = av.w;
            Bs[nb][0][tid] = bv0.x; Bs[nb][1][tid] = bv0.y;
            Bs[nb][2][tid] = bv0.z; Bs[nb][3][tid] = bv0.w;
            Bs[nb][4][tid] = bv1.x; Bs[nb][5][tid] = bv1.y;
            Bs[nb][6][tid] = bv1.z; Bs[nb][7][tid] = bv1.w;
            __syncthreads();
            buf = nb;
        }
    }

#pragma unroll
    for (int i = 0; i < 8; i++) {
        float* crow = C + (size_t)(m0 + ty * 8 + i) * N + n0 + tx * 4;
#pragma unroll
        for (int g = 0; g < 4; g++) {
            U2 v; v.x = acc[i][2 * g]; v.y = acc[i][2 * g + 1];
            *(U2*)(crow + g * 64) = v;
        }
    }
}

// ---------------------------------------------------------------------------
// kq_kernel: g_kq[b*S+t] = K[b,t,:] . Q[b,t,:]   (one warp per row)
// ---------------------------------------------------------------------------
__global__ __launch_bounds__(256) void kq_kernel()
{
    const int row  = (blockIdx.x * blockDim.x + threadIdx.x) >> 5; // 0..16383
    const int lane = threadIdx.x & 31;
    const U2* kp = (const U2*)(g_K + (size_t)row * D_DIM);
    const U2* qp = (const U2*)(g_Q + (size_t)row * D_DIM);
    unsigned long long acc = 0ULL;
#pragma unroll
    for (int j = 0; j < 8; j++) {
        U2 k = kp[lane + 32 * j];
        U2 q = qp[lane + 32 * j];
        acc = f2fma(k.x, q.x, acc);
        acc = f2fma(k.y, q.y, acc);
    }
    unsigned long long s = warp_sum_pair(acc);
    if (lane == 0) g_kq[row] = f2hsum(s);
}

// ---------------------------------------------------------------------------
// scan_kernel: CTA = 256 threads = 8 warps, one batch b, 32 e-rows
// (4 consecutive per warp, register-resident W = 128 regs/lane).
// k_t / q_t staged cooperatively into double-buffered SMEM (8KB/step):
// each thread LDGs one float4 of k and q for step t+1 at the top of step t,
// STS after compute, one __syncthreads per step -> no exposed LDG latency.
// Dots read SMEM via LDS.64 (lane*8B: conflict-free), hidden under FMA issue.
// ---------------------------------------------------------------------------
__global__ __launch_bounds__(256, 1) void scan_kernel(
    const float* __restrict__ W0,
    const float* __restrict__ b0,
    float* __restrict__ out)
{
    __shared__ __align__(16) float sk[2][D_DIM];
    __shared__ __align__(16) float sq[2][D_DIM];

    const int tid  = threadIdx.x;
    const int lane = tid & 31;
    const int w    = tid >> 5;
    const int b    = blockIdx.y;
    const int e0   = blockIdx.x * 32 + 4 * w;   // multiple of 4

    // init state: W rows e0..e0+3 and biases
    unsigned long long Wr[4][16];
    float bb[4];
#pragma unroll
    for (int r = 0; r < 4; r++) {
        const U2* p = (const U2*)(W0 + (size_t)(e0 + r) * D_DIM);
#pragma unroll
        for (int j = 0; j < 8; j++) {
            U2 t = p[lane + 32 * j];
            Wr[r][2 * j] = t.x; Wr[r][2 * j + 1] = t.y;
        }
        bb[r] = b0[e0 + r];
    }

    const size_t base = (size_t)b * S_DIM * D_DIM;
    const float*  Kb  = g_K + base;
    const float*  Qb  = g_Q + base;
    const float4* Vp  = (const float4*)(g_V + base + e0);   // e0 % 4 == 0
    const float*  kqp = g_kq + (size_t)b * S_DIM;
    float4* outp      = (float4*)(out + base + e0);

    // prologue: stage t = 0
    {
        float4 k0v = *(const float4*)(Kb + tid * 4);
        float4 q0v = *(const float4*)(Qb + tid * 4);
        *(float4*)&sk[0][tid * 4] = k0v;
        *(float4*)&sq[0][tid * 4] = q0v;
    }
    __syncthreads();

    int cur = 0;
    for (int t = 0; t < S_DIM; t++) {
        // prefetch t+1 into registers (consumed after compute)
        float4 pk, pq;
        const bool more = (t + 1) < S_DIM;
        if (more) {
            pk = *(const float4*)(Kb + (size_t)(t + 1) * D_DIM + tid * 4);
            pq = *(const float4*)(Qb + (size_t)(t + 1) * D_DIM + tid * 4);
        }
        // epilogue scalars (issued early, hidden under FMAs)
        float4 v  = Vp[(size_t)t * (D_DIM / 4)];
        float kq1 = kqp[t] + 1.0f;

        const U2* kp = (const U2*)&sk[cur][0];
        const U2* qp = (const U2*)&sq[cur][0];
        unsigned long long ak[4] = {0ULL, 0ULL, 0ULL, 0ULL};
        unsigned long long aq[4] = {0ULL, 0ULL, 0ULL, 0ULL};
        U2 ksave[8];
#pragma unroll
        for (int j = 0; j < 8; j++) {
            U2 kj = kp[lane + 32 * j];
            U2 qj = qp[lane + 32 * j];
            ksave[j] = kj;
#pragma unroll
            for (int r = 0; r < 4; r++) {
                ak[r] = f2fma(Wr[r][2 * j],     kj.x, ak[r]);
                ak[r] = f2fma(Wr[r][2 * j + 1], kj.y, ak[r]);
                aq[r] = f2fma(Wr[r][2 * j],     qj.x, aq[r]);
                aq[r] = f2fma(Wr[r][2 * j + 1], qj.y, aq[r]);
            }
        }
        // pack (d1[r], d2[r]) per row, butterfly pairs across the warp
        float d1[4], d2[4];
#pragma unroll
        for (int r = 0; r < 4; r++) {
            unsigned long long pr = f2pack(f2hsum(ak[r]), f2hsum(aq[r]));
            pr = warp_sum_pair(pr);
            f2unpack(pr, d1[r], d2[r]);
        }
        float og[4];
        og[0] = (LR_F * C1_F) * (d1[0] + bb[0] - v.x);
        og[1] = (LR_F * C1_F) * (d1[1] + bb[1] - v.y);
        og[2] = (LR_F * C1_F) * (d1[2] + bb[2] - v.z);
        og[3] = (LR_F * C1_F) * (d1[3] + bb[3] - v.w);
        if (lane == 0) {
            float4 o;
            o.x = d2[0] + bb[0] - og[0] * kq1;
            o.y = d2[1] + bb[1] - og[1] * kq1;
            o.z = d2[2] + bb[2] - og[2] * kq1;
            o.w = d2[3] + bb[3] - og[3] * kq1;
            outp[(size_t)t * (D_DIM / 4)] = o;
        }
        unsigned long long nog[4];
#pragma unroll
        for (int r = 0; r < 4; r++) nog[r] = f2pack(-og[r], -og[r]);
#pragma unroll
        for (int j = 0; j < 8; j++) {
#pragma unroll
            for (int r = 0; r < 4; r++) {
                Wr[r][2 * j]     = f2fma(nog[r], ksave[j].x, Wr[r][2 * j]);
                Wr[r][2 * j + 1] = f2fma(nog[r], ksave[j].y, Wr[r][2 * j + 1]);
            }
        }
#pragma unroll
        for (int r = 0; r < 4; r++) bb[r] -= og[r];

        // stage t+1 into the other buffer (safe: compute read buf `cur` only,
        // and the barrier below orders these writes before next step's reads)
        if (more) {
            *(float4*)&sk[cur ^ 1][tid * 4] = pk;
            *(float4*)&sq[cur ^ 1][tid * 4] = pq;
        }
        __syncthreads();
        cur ^= 1;
    }
}

// ---------------------------------------------------------------------------
extern "C" void kernel_launch(void* const* d_in, const int* in_sizes, int n_in,
                              void* d_out, int out_size)
{
    (void)in_sizes; (void)n_in; (void)out_size;
    const float* in_seq = (const float*)d_in[0];
    const float* thK    = (const float*)d_in[1];
    const float* thV    = (const float*)d_in[2];
    const float* thQ    = (const float*)d_in[3];
    const float* W0     = (const float*)d_in[4];
    const float* b0     = (const float*)d_in[5];
    float* out          = (float*)d_out;

    // 1) K/V/Q projections: [16384,1024] x [1024,1024]^T, z selects theta
    dim3 pgrid(16384 / 128, D_DIM / 256, 3);
    proj_kernel<<<pgrid, 256>>>(in_seq, thK, thV, thQ);

    // 2) per-token k.q
    kq_kernel<<<(B_DIM * S_DIM) / 8, 256>>>();

    // 3) sequential scan, CTA per (batch, 32 e-rows), smem-staged k/q
    dim3 sgrid(D_DIM / 32, B_DIM);
    scan_kernel<<<sgrid, 256>>>(W0, b0, out);
}

// round 15
// speedup vs baseline: 1.2782x; 1.1567x over previous
#include <cuda_runtime.h>
#include <cuda_bf16.h>
#include <cstdint>

// ---------------------------------------------------------------------------
// TTT layer, B=8, S=2048, D_IN=D_H=1024, fp32.
// R15 == audited R12/R13/R14 (never ran): scan -> TWO-token phases, exact
// rank-1 correction algebra; one reduction + one scalar tail + one barrier
// per 2 tokens. Cross scalars {k0.q0, k0.k1, k0.q1, k1.q1} from kq4_kernel.
// proj unchanged (R11-measured 1.95ms, fma 66%): conflict-free chunked B.
// ---------------------------------------------------------------------------

#define B_DIM   8
#define S_DIM   2048
#define D_DIM   1024
#define LR_F    0.01f
#define C1_F    (2.0f / 1024.0f)

__device__ __align__(16) float g_K[B_DIM * S_DIM * D_DIM];
__device__ __align__(16) float g_V[B_DIM * S_DIM * D_DIM];
__device__ __align__(16) float g_Q[B_DIM * S_DIM * D_DIM];
__device__ __align__(16) float g_kq4[(B_DIM * S_DIM / 2) * 4]; // per 2-token group

// ---------------- packed f32x2 helpers (PTX-only on sm_103a) ----------------
struct __align__(16) U2 { unsigned long long x, y; };

__device__ __forceinline__ unsigned long long f2fma(unsigned long long a,
                                                    unsigned long long b,
                                                    unsigned long long c) {
    unsigned long long d;
    asm("fma.rn.f32x2 %0, %1, %2, %3;" : "=l"(d) : "l"(a), "l"(b), "l"(c));
    return d;
}
__device__ __forceinline__ unsigned long long f2add(unsigned long long a,
                                                    unsigned long long b) {
    unsigned long long d;
    asm("add.rn.f32x2 %0, %1, %2;" : "=l"(d) : "l"(a), "l"(b));
    return d;
}
__device__ __forceinline__ unsigned long long f2pack(float lo, float hi) {
    unsigned long long d;
    asm("mov.b64 %0, {%1, %2};" : "=l"(d) : "f"(lo), "f"(hi));
    return d;
}
__device__ __forceinline__ void f2unpack(unsigned long long v, float& lo, float& hi) {
    asm("mov.b64 {%0, %1}, %2;" : "=f"(lo), "=f"(hi) : "l"(v));
}
__device__ __forceinline__ float f2hsum(unsigned long long v) {
    float lo, hi; f2unpack(v, lo, hi);
    return lo + hi;
}
// Butterfly all-reduce of a packed f32x2 pair (64-bit shfl + packed add).
__device__ __forceinline__ unsigned long long warp_sum_pair(unsigned long long v) {
#pragma unroll
    for (int off = 16; off; off >>= 1) {
        unsigned long long s = __shfl_xor_sync(0xffffffffu, v, off);
        v = f2add(v, s);
    }
    return v;
}

// ---------------------------------------------------------------------------
// Projection GEMM (R11-proven): 128x256 tile, BK=8, 256 threads,
// chunked conflict-free B fragment (n = tx*4 + g*64), double-buffered SMEM.
// ---------------------------------------------------------------------------
__global__ __launch_bounds__(256, 1) void proj_kernel(
    const float* __restrict__ A,
    const float* __restrict__ thK,
    const float* __restrict__ thV,
    const float* __restrict__ thQ)
{
    constexpr int K = D_DIM, N = D_DIM;
    const float* __restrict__ Bm;
    float* __restrict__ C;
    if (blockIdx.z == 0)      { Bm = thK; C = g_K; }
    else if (blockIdx.z == 1) { Bm = thV; C = g_V; }
    else                      { Bm = thQ; C = g_Q; }

    __shared__ __align__(16) float As[2][8][128];
    __shared__ __align__(16) float Bs[2][8][256];

    const int tid  = threadIdx.x;
    const int m0   = blockIdx.x * 128;
    const int n0   = blockIdx.y * 256;
    const int lrow = tid >> 1;
    const int lcol = (tid & 1) << 2;
    const float* Ap = A  + (size_t)(m0 + lrow) * K + lcol;
    const float* Bp = Bm + (size_t)(n0 + tid) * K;
    const int tx = tid & 15;
    const int ty = tid >> 4;

    unsigned long long acc[8][8];
#pragma unroll
    for (int i = 0; i < 8; i++)
#pragma unroll
        for (int j = 0; j < 8; j++) acc[i][j] = 0ULL;

    {
        float4 av  = *(const float4*)(Ap);
        float4 bv0 = *(const float4*)(Bp);
        float4 bv1 = *(const float4*)(Bp + 4);
        As[0][lcol + 0][lrow] = av.x; As[0][lcol + 1][lrow] = av.y;
        As[0][lcol + 2][lrow] = av.z; As[0][lcol + 3][lrow] = av.w;
        Bs[0][0][tid] = bv0.x; Bs[0][1][tid] = bv0.y;
        Bs[0][2][tid] = bv0.z; Bs[0][3][tid] = bv0.w;
        Bs[0][4][tid] = bv1.x; Bs[0][5][tid] = bv1.y;
        Bs[0][6][tid] = bv1.z; Bs[0][7][tid] = bv1.w;
    }
    __syncthreads();

    int buf = 0;
    for (int k0 = 0; k0 < K; k0 += 8) {
        float4 av, bv0, bv1;
        const bool more = (k0 + 8) < K;
        if (more) {
            av  = *(const float4*)(Ap + k0 + 8);
            bv0 = *(const float4*)(Bp + k0 + 8);
            bv1 = *(const float4*)(Bp + k0 + 12);
        }
#pragma unroll
        for (int kk = 0; kk < 8; kk++) {
            float4 a0 = *(const float4*)&As[buf][kk][ty * 8];
            float4 a1 = *(const float4*)&As[buf][kk][ty * 8 + 4];
            U2 bg[4];
#pragma unroll
            for (int g = 0; g < 4; g++)
                bg[g] = *(const U2*)&Bs[buf][kk][tx * 4 + g * 64];
            float a[8] = {a0.x, a0.y, a0.z, a0.w, a1.x, a1.y, a1.z, a1.w};
#pragma unroll
            for (int i = 0; i < 8; i++) {
                unsigned long long ra = f2pack(a[i], a[i]);
#pragma unroll
                for (int g = 0; g < 4; g++) {
                    acc[i][2 * g]     = f2fma(ra, bg[g].x, acc[i][2 * g]);
                    acc[i][2 * g + 1] = f2fma(ra, bg[g].y, acc[i][2 * g + 1]);
                }
            }
        }
        if (more) {
            const int nb = buf ^ 1;
            As[nb][lcol + 0][lrow] = av.x; As[nb][lcol + 1][lrow] = av.y;
            As[nb][lcol + 2][lrow] = av.z; As[nb][lcol + 3][lrow] = av.w;
            Bs[nb][0][tid] = bv0.x; Bs[nb][1][tid] = bv0.y;
            Bs[nb][2][tid] = bv0.z; Bs[nb][3][tid] = bv0.w;
            Bs[nb][4][tid] = bv1.x; Bs[nb][5][tid] = bv1.y;
            Bs[nb][6][tid] = bv1.z; Bs[nb][7][tid] = bv1.w;
            __syncthreads();
            buf = nb;
        }
    }

#pragma unroll
    for (int i = 0; i < 8; i++) {
        float* crow = C + (size_t)(m0 + ty * 8 + i) * N + n0 + tx * 4;
#pragma unroll
        for (int g = 0; g < 4; g++) {
            U2 v; v.x = acc[i][2 * g]; v.y = acc[i][2 * g + 1];
            *(U2*)(crow + g * 64) = v;
        }
    }
}

// ---------------------------------------------------------------------------
// kq4_kernel: one warp per 2-token group m (tokens t0=2m, t1=2m+1):
//   g_kq4[4m..4m+3] = { k0.q0, k0.k1, k0.q1, k1.q1 }
// ---------------------------------------------------------------------------
__global__ __launch_bounds__(256) void kq4_kernel()
{
    const int grp  = (blockIdx.x * blockDim.x + threadIdx.x) >> 5; // 0..B*S/2-1
    const int lane = threadIdx.x & 31;
    const size_t r0 = (size_t)grp * 2 * D_DIM;
    const U2* k0p = (const U2*)(g_K + r0);
    const U2* q0p = (const U2*)(g_Q + r0);
    const U2* k1p = (const U2*)(g_K + r0 + D_DIM);
    const U2* q1p = (const U2*)(g_Q + r0 + D_DIM);
    unsigned long long a00 = 0ULL, a01k = 0ULL, a01q = 0ULL, a11 = 0ULL;
#pragma unroll
    for (int j = 0; j < 8; j++) {
        U2 k0 = k0p[lane + 32 * j];
        U2 q0 = q0p[lane + 32 * j];
        U2 k1 = k1p[lane + 32 * j];
        U2 q1 = q1p[lane + 32 * j];
        a00  = f2fma(k0.x, q0.x, a00);  a00  = f2fma(k0.y, q0.y, a00);
        a01k = f2fma(k0.x, k1.x, a01k); a01k = f2fma(k0.y, k1.y, a01k);
        a01q = f2fma(k0.x, q1.x, a01q); a01q = f2fma(k0.y, q1.y, a01q);
        a11  = f2fma(k1.x, q1.x, a11);  a11  = f2fma(k1.y, q1.y, a11);
    }
    unsigned long long p0 = f2pack(f2hsum(a00),  f2hsum(a01k));
    unsigned long long p1 = f2pack(f2hsum(a01q), f2hsum(a11));
    p0 = warp_sum_pair(p0);
    p1 = warp_sum_pair(p1);
    if (lane == 0) {
        float x, y, z, w;
        f2unpack(p0, x, y);
        f2unpack(p1, z, w);
        *(float4*)&g_kq4[4 * grp] = make_float4(x, y, z, w);
    }
}

// ---------------------------------------------------------------------------
// scan_kernel: CTA = 256 threads = 8 warps, batch b, 32 e-rows
// (4 per warp, W register-resident = 128 regs/lane). TWO tokens per phase:
// both tokens' dots use chunk-start W; exact corrections via precomputed
// cross scalars; single reduction (8 stage-parallel butterflies), single
// scalar tail, single barrier per 2 tokens. k re-read from SMEM in update.
// ---------------------------------------------------------------------------
__global__ __launch_bounds__(256, 1) void scan_kernel(
    const float* __restrict__ W0,
    const float* __restrict__ b0,
    float* __restrict__ out)
{
    __shared__ __align__(16) float sk0[2][D_DIM];
    __shared__ __align__(16) float sq0[2][D_DIM];
    __shared__ __align__(16) float sk1[2][D_DIM];
    __shared__ __align__(16) float sq1[2][D_DIM];

    const int tid  = threadIdx.x;
    const int lane = tid & 31;
    const int w    = tid >> 5;
    const int b    = blockIdx.y;
    const int e0   = blockIdx.x * 32 + 4 * w;   // multiple of 4

    unsigned long long Wr[4][16];
    float bb[4];
#pragma unroll
    for (int r = 0; r < 4; r++) {
        const U2* p = (const U2*)(W0 + (size_t)(e0 + r) * D_DIM);
#pragma unroll
        for (int j = 0; j < 8; j++) {
            U2 t = p[lane + 32 * j];
            Wr[r][2 * j] = t.x; Wr[r][2 * j + 1] = t.y;
        }
        bb[r] = b0[e0 + r];
    }

    const size_t base = (size_t)b * S_DIM * D_DIM;
    const float*  Kb   = g_K + base;
    const float*  Qb   = g_Q + base;
    const float4* Vp   = (const float4*)(g_V + base + e0);
    const float*  kq4p = g_kq4 + (size_t)b * (S_DIM / 2) * 4;
    float4* outp       = (float4*)(out + base + e0);

    // prologue: stage phase 0 (tokens 0, 1)
    {
        *(float4*)&sk0[0][tid * 4] = *(const float4*)(Kb + tid * 4);
        *(float4*)&sq0[0][tid * 4] = *(const float4*)(Qb + tid * 4);
        *(float4*)&sk1[0][tid * 4] = *(const float4*)(Kb + D_DIM + tid * 4);
        *(float4*)&sq1[0][tid * 4] = *(const float4*)(Qb + D_DIM + tid * 4);
    }
    __syncthreads();

    int cur = 0;
    for (int p = 0; p < S_DIM / 2; p++) {
        const int t0 = 2 * p;
        // prefetch next phase into registers
        float4 pk0, pq0, pk1, pq1;
        const bool more = (p + 1) < (S_DIM / 2);
        if (more) {
            const size_t nb0 = (size_t)(t0 + 2) * D_DIM + tid * 4;
            pk0 = *(const float4*)(Kb + nb0);
            pq0 = *(const float4*)(Qb + nb0);
            pk1 = *(const float4*)(Kb + nb0 + D_DIM);
            pq1 = *(const float4*)(Qb + nb0 + D_DIM);
        }
        // epilogue scalars, issued early
        float4 cc = *(const float4*)&kq4p[4 * p];   // {k0.q0, k0.k1, k0.q1, k1.q1}
        float4 v0 = Vp[(size_t)t0 * (D_DIM / 4)];
        float4 v1 = Vp[(size_t)(t0 + 1) * (D_DIM / 4)];

        const U2* k0p = (const U2*)&sk0[cur][0];
        const U2* q0p = (const U2*)&sq0[cur][0];
        const U2* k1p = (const U2*)&sk1[cur][0];
        const U2* q1p = (const U2*)&sq1[cur][0];

        unsigned long long ak0[4] = {0,0,0,0}, aq0[4] = {0,0,0,0};
        unsigned long long ak1[4] = {0,0,0,0}, aq1[4] = {0,0,0,0};
#pragma unroll
        for (int j = 0; j < 8; j++) {
            U2 k0 = k0p[lane + 32 * j];
            U2 q0 = q0p[lane + 32 * j];
            U2 k1 = k1p[lane + 32 * j];
            U2 q1 = q1p[lane + 32 * j];
#pragma unroll
            for (int r = 0; r < 4; r++) {
                ak0[r] = f2fma(Wr[r][2 * j],     k0.x, ak0[r]);
                ak0[r] = f2fma(Wr[r][2 * j + 1], k0.y, ak0[r]);
                aq0[r] = f2fma(Wr[r][2 * j],     q0.x, aq0[r]);
                aq0[r] = f2fma(Wr[r][2 * j + 1], q0.y, aq0[r]);
                ak1[r] = f2fma(Wr[r][2 * j],     k1.x, ak1[r]);
                ak1[r] = f2fma(Wr[r][2 * j + 1], k1.y, ak1[r]);
                aq1[r] = f2fma(Wr[r][2 * j],     q1.x, aq1[r]);
                aq1[r] = f2fma(Wr[r][2 * j + 1], q1.y, aq1[r]);
            }
        }
        // 8 stage-parallel butterflies: pr[r] = (d1_0, d2_0), pr[4+r] = (d1_1, d2_1)
        unsigned long long pr[8];
#pragma unroll
        for (int r = 0; r < 4; r++) {
            pr[r]     = f2pack(f2hsum(ak0[r]), f2hsum(aq0[r]));
            pr[4 + r] = f2pack(f2hsum(ak1[r]), f2hsum(aq1[r]));
        }
#pragma unroll
        for (int off = 16; off; off >>= 1) {
            unsigned long long s[8];
#pragma unroll
            for (int i = 0; i < 8; i++) s[i] = __shfl_xor_sync(0xffffffffu, pr[i], off);
#pragma unroll
            for (int i = 0; i < 8; i++) pr[i] = f2add(pr[i], s[i]);
        }
        // scalar tail (once per 2 tokens)
        const float c00 = cc.x + 1.0f;   // k0.q0 + 1
        const float c01 = cc.y + 1.0f;   // k0.k1 + 1
        const float c02 = cc.z + 1.0f;   // k0.q1 + 1
        const float c11 = cc.w + 1.0f;   // k1.q1 + 1
        float vv0[4] = {v0.x, v0.y, v0.z, v0.w};
        float vv1[4] = {v1.x, v1.y, v1.z, v1.w};
        float og0[4], og1[4], o0[4], o1[4];
#pragma unroll
        for (int r = 0; r < 4; r++) {
            float d10, d20, d11, d21;
            f2unpack(pr[r], d10, d20);
            f2unpack(pr[4 + r], d11, d21);
            og0[r] = (LR_F * C1_F) * (d10 + bb[r] - vv0[r]);
            o0[r]  = d20 + bb[r] - og0[r] * c00;
            float pred1 = d11 + bb[r] - og0[r] * c01;
            og1[r] = (LR_F * C1_F) * (pred1 - vv1[r]);
            o1[r]  = d21 + bb[r] - og0[r] * c02 - og1[r] * c11;
            bb[r] -= og0[r] + og1[r];
        }
        if (lane == 0) {
            outp[(size_t)t0 * (D_DIM / 4)]       = make_float4(o0[0], o0[1], o0[2], o0[3]);
            outp[(size_t)(t0 + 1) * (D_DIM / 4)] = make_float4(o1[0], o1[1], o1[2], o1[3]);
        }
        // W update: W -= og0 k0 + og1 k1 (k re-read from SMEM; regs saved)
        unsigned long long n0[4], n1[4];
#pragma unroll
        for (int r = 0; r < 4; r++) {
            n0[r] = f2pack(-og0[r], -og0[r]);
            n1[r] = f2pack(-og1[r], -og1[r]);
        }
#pragma unroll
        for (int j = 0; j < 8; j++) {
            U2 k0 = k0p[lane + 32 * j];
            U2 k1 = k1p[lane + 32 * j];
#pragma unroll
            for (int r = 0; r < 4; r++) {
                Wr[r][2 * j]     = f2fma(n0[r], k0.x, Wr[r][2 * j]);
                Wr[r][2 * j]     = f2fma(n1[r], k1.x, Wr[r][2 * j]);
                Wr[r][2 * j + 1] = f2fma(n0[r], k0.y, Wr[r][2 * j + 1]);
                Wr[r][2 * j + 1] = f2fma(n1[r], k1.y, Wr[r][2 * j + 1]);
            }
        }
        // stage next phase into other buffer (readers used buf `cur` only)
        if (more) {
            *(float4*)&sk0[cur ^ 1][tid * 4] = pk0;
            *(float4*)&sq0[cur ^ 1][tid * 4] = pq0;
            *(float4*)&sk1[cur ^ 1][tid * 4] = pk1;
            *(float4*)&sq1[cur ^ 1][tid * 4] = pq1;
        }
        __syncthreads();
        cur ^= 1;
    }
}

// ---------------------------------------------------------------------------
extern "C" void kernel_launch(void* const* d_in, const int* in_sizes, int n_in,
                              void* d_out, int out_size)
{
    (void)in_sizes; (void)n_in; (void)out_size;
    const float* in_seq = (const float*)d_in[0];
    const float* thK    = (const float*)d_in[1];
    const float* thV    = (const float*)d_in[2];
    const float* thQ    = (const float*)d_in[3];
    const float* W0     = (const float*)d_in[4];
    const float* b0     = (const float*)d_in[5];
    float* out          = (float*)d_out;

    // 1) K/V/Q projections
    dim3 pgrid(16384 / 128, D_DIM / 256, 3);
    proj_kernel<<<pgrid, 256>>>(in_seq, thK, thV, thQ);

    // 2) per-group cross dot products (k0.q0, k0.k1, k0.q1, k1.q1)
    kq4_kernel<<<(B_DIM * S_DIM / 2) / 8, 256>>>();

    // 3) sequential scan, 2 tokens per phase
    dim3 sgrid(D_DIM / 32, B_DIM);
    scan_kernel<<<sgrid, 256>>>(W0, b0, out);
}